// round 1
// baseline (speedup 1.0000x reference)
#include <cuda_runtime.h>

#define FULLMASK 0xffffffffu

// Problem sizes (fixed by the dataset)
#define CN 50000
#define CE 800000

// ---------------- scratch (device globals; no cudaMalloc allowed) -------------
__device__ float g_Ah[CN * 64];
__device__ float g_Bh[CN * 64];
__device__ float g_Ch[CN * 64];
__device__ float g_Dh[CN * 64];
__device__ float g_h2[CN * 64];
__device__ float g_ss[CN * 64];    // sum_sigma
__device__ float g_ssh[CN * 64];   // sum_sigma_h
__device__ float g_e2[CE * 64];    // e after residual (input to FFN-e)
__device__ float g_stats[4 * 128]; // [set][sum(64) | sumsq(64)]
__device__ float g_scale[4 * 64];  // folded BN: y = x*scale + shift
__device__ float g_shift[4 * 64];

// ---------------- zero scratch that is accumulated into -----------------------
__global__ void k_zero(int node_elems) {
    int i = blockIdx.x * blockDim.x + threadIdx.x;
    int stride = gridDim.x * blockDim.x;
    for (int j = i; j < node_elems; j += stride) {
        g_ss[j] = 0.f;
        g_ssh[j] = 0.f;
    }
    if (i < 4 * 128) g_stats[i] = 0.f;
}

// ---------------- column mean/var stats (sum + sumsq) -------------------------
__global__ __launch_bounds__(256) void k_stats(const float* __restrict__ x, int rows, int set) {
    __shared__ float ssum[64], ssq[64];
    int tid = threadIdx.x;
    if (tid < 64) { ssum[tid] = 0.f; ssq[tid] = 0.f; }
    __syncthreads();
    int cg = tid & 15;                                  // column group (4 cols)
    int r = (blockIdx.x * blockDim.x + tid) >> 4;
    int rstride = (gridDim.x * blockDim.x) >> 4;
    float4 s = make_float4(0, 0, 0, 0), q = make_float4(0, 0, 0, 0);
    for (; r < rows; r += rstride) {
        float4 v = *(const float4*)(x + (size_t)r * 64 + cg * 4);
        s.x += v.x; s.y += v.y; s.z += v.z; s.w += v.w;
        q.x += v.x * v.x; q.y += v.y * v.y; q.z += v.z * v.z; q.w += v.w * v.w;
    }
    atomicAdd(&ssum[cg * 4 + 0], s.x); atomicAdd(&ssum[cg * 4 + 1], s.y);
    atomicAdd(&ssum[cg * 4 + 2], s.z); atomicAdd(&ssum[cg * 4 + 3], s.w);
    atomicAdd(&ssq[cg * 4 + 0], q.x);  atomicAdd(&ssq[cg * 4 + 1], q.y);
    atomicAdd(&ssq[cg * 4 + 2], q.z);  atomicAdd(&ssq[cg * 4 + 3], q.w);
    __syncthreads();
    if (tid < 64) {
        atomicAdd(&g_stats[set * 128 + tid], ssum[tid]);
        atomicAdd(&g_stats[set * 128 + 64 + tid], ssq[tid]);
    }
}

// ---------------- fold BN into scale/shift -------------------------------------
__global__ void k_finalize(int set, const float* __restrict__ gamma,
                           const float* __restrict__ beta, float inv_count) {
    int t = threadIdx.x;  // 64 threads
    float mean = g_stats[set * 128 + t] * inv_count;
    float var = g_stats[set * 128 + 64 + t] * inv_count - mean * mean;
    float sc = gamma[t] * rsqrtf(var + 1e-5f);
    g_scale[set * 64 + t] = sc;
    g_shift[set * 64 + t] = beta[t] - mean * sc;
}

// ---------------- node linears: Ah,Bh,Ch,Dh = bn1(h) @ {A,B,C,D}w + b ---------
__global__ __launch_bounds__(256) void k_node(
    const float* __restrict__ h,
    const float* __restrict__ Aw, const float* __restrict__ Bw,
    const float* __restrict__ Cw, const float* __restrict__ Dw,
    const float* __restrict__ Ab, const float* __restrict__ Bb,
    const float* __restrict__ Cb, const float* __restrict__ Db,
    int rows) {
    extern __shared__ float sw[];  // 4 * 64*64
    for (int i = threadIdx.x; i < 4096; i += blockDim.x) {
        sw[i] = Aw[i]; sw[4096 + i] = Bw[i]; sw[8192 + i] = Cw[i]; sw[12288 + i] = Dw[i];
    }
    __syncthreads();
    int lane = threadIdx.x & 31;
    int warp = (blockIdx.x * blockDim.x + threadIdx.x) >> 5;
    int nw = (gridDim.x * blockDim.x) >> 5;
    int c = lane * 2;
    float2 sc = *(const float2*)(g_scale + c);       // set 0
    float2 sh = *(const float2*)(g_shift + c);
    float2 ab = *(const float2*)(Ab + c);
    float2 bb = *(const float2*)(Bb + c);
    float2 cb = *(const float2*)(Cb + c);
    float2 db = *(const float2*)(Db + c);
    for (int r = warp; r < rows; r += nw) {
        float2 hv = *(const float2*)(h + (size_t)r * 64 + c);
        float x0 = hv.x * sc.x + sh.x;
        float x1 = hv.y * sc.y + sh.y;
        float2 aA = ab, aB = bb, aC = cb, aD = db;
#pragma unroll 4
        for (int s = 0; s < 32; s++) {
            float xa = __shfl_sync(FULLMASK, x0, s);
            float xb = __shfl_sync(FULLMASK, x1, s);
            int k0 = (2 * s) * 64 + c, k1 = (2 * s + 1) * 64 + c;
            float2 wa, wb;
            wa = *(float2*)(sw + k0); wb = *(float2*)(sw + k1);
            aA.x += xa * wa.x + xb * wb.x; aA.y += xa * wa.y + xb * wb.y;
            wa = *(float2*)(sw + 4096 + k0); wb = *(float2*)(sw + 4096 + k1);
            aB.x += xa * wa.x + xb * wb.x; aB.y += xa * wa.y + xb * wb.y;
            wa = *(float2*)(sw + 8192 + k0); wb = *(float2*)(sw + 8192 + k1);
            aC.x += xa * wa.x + xb * wb.x; aC.y += xa * wa.y + xb * wb.y;
            wa = *(float2*)(sw + 12288 + k0); wb = *(float2*)(sw + 12288 + k1);
            aD.x += xa * wa.x + xb * wb.x; aD.y += xa * wa.y + xb * wb.y;
        }
        size_t o = (size_t)r * 64 + c;
        *(float2*)(g_Ah + o) = aA;
        *(float2*)(g_Bh + o) = aB;
        *(float2*)(g_Ch + o) = aC;
        *(float2*)(g_Dh + o) = aD;
    }
}

// ---------------- edge kernel: e_new, sigma, segment sums, e2 + its stats ------
// warp processes 4 edges at a time (weight smem loads amortized 4x)
__global__ __launch_bounds__(256) void k_edge(
    const float* __restrict__ e, const int* __restrict__ src, const int* __restrict__ dst,
    const float* __restrict__ Ew, const float* __restrict__ Eb, int ecount) {
    __shared__ float sm[4096 + 8 * 256];  // Ew + per-warp x staging (4 rows x 64)
    float* sw = sm;
    float* xs = sm + 4096 + (threadIdx.x >> 5) * 256;
    for (int i = threadIdx.x; i < 4096; i += blockDim.x) sw[i] = Ew[i];
    __syncthreads();
    int lane = threadIdx.x & 31;
    int warp = (blockIdx.x * blockDim.x + threadIdx.x) >> 5;
    int nw = (gridDim.x * blockDim.x) >> 5;
    int c = lane * 2;
    float2 sc = *(const float2*)(g_scale + 64 + c);  // set 1 (e)
    float2 sh = *(const float2*)(g_shift + 64 + c);
    float2 eb = *(const float2*)(Eb + c);
    float st_s0 = 0.f, st_s1 = 0.f, st_q0 = 0.f, st_q1 = 0.f;
    int ngroups = ecount >> 2;  // E divisible by 4
    for (int g = warp; g < ngroups; g += nw) {
        int ebase = g * 4;
        float2 raw[4];
#pragma unroll
        for (int r = 0; r < 4; r++) {
            float2 ev = *(const float2*)(e + (size_t)(ebase + r) * 64 + c);
            raw[r] = ev;
            *(float2*)(xs + r * 64 + c) = make_float2(ev.x * sc.x + sh.x, ev.y * sc.y + sh.y);
        }
        __syncwarp();
        float2 acc[4] = {eb, eb, eb, eb};
#pragma unroll 4
        for (int s = 0; s < 32; s++) {
            float2 wa = *(float2*)(sw + (2 * s) * 64 + c);
            float2 wb = *(float2*)(sw + (2 * s + 1) * 64 + c);
#pragma unroll
            for (int r = 0; r < 4; r++) {
                float2 xv = *(float2*)(xs + r * 64 + 2 * s);   // broadcast
                acc[r].x += xv.x * wa.x + xv.y * wb.x;
                acc[r].y += xv.x * wa.y + xv.y * wb.y;
            }
        }
        __syncwarp();
#pragma unroll
        for (int r = 0; r < 4; r++) {
            int eidx = ebase + r;
            int sI = src[eidx], dI = dst[eidx];
            float2 ch = *(const float2*)(g_Ch + (size_t)sI * 64 + c);
            float2 dh = *(const float2*)(g_Dh + (size_t)dI * 64 + c);
            float en0 = acc[r].x + ch.x + dh.x;
            float en1 = acc[r].y + ch.y + dh.y;
            float e20 = raw[r].x + en0, e21 = raw[r].y + en1;
            *(float2*)(g_e2 + (size_t)eidx * 64 + c) = make_float2(e20, e21);
            st_s0 += e20; st_q0 += e20 * e20;
            st_s1 += e21; st_q1 += e21 * e21;
            float sg0 = 1.f / (1.f + __expf(-en0));
            float sg1 = 1.f / (1.f + __expf(-en1));
            float2 bh = *(const float2*)(g_Bh + (size_t)sI * 64 + c);
            size_t o = (size_t)dI * 64 + c;
            atomicAdd(g_ss + o, sg0);
            atomicAdd(g_ss + o + 1, sg1);
            atomicAdd(g_ssh + o, bh.x * sg0);
            atomicAdd(g_ssh + o + 1, bh.y * sg1);
        }
    }
    // e2 stats -> set 3
    atomicAdd(&g_stats[3 * 128 + c], st_s0);
    atomicAdd(&g_stats[3 * 128 + c + 1], st_s1);
    atomicAdd(&g_stats[3 * 128 + 64 + c], st_q0);
    atomicAdd(&g_stats[3 * 128 + 64 + c + 1], st_q1);
}

// ---------------- h2 = h + Ah + ssh/(ss+eps), plus its stats -------------------
__global__ __launch_bounds__(256) void k_h2(const float* __restrict__ h, int rows) {
    int lane = threadIdx.x & 31;
    int warp = (blockIdx.x * blockDim.x + threadIdx.x) >> 5;
    int nw = (gridDim.x * blockDim.x) >> 5;
    int c = lane * 2;
    float st_s0 = 0.f, st_s1 = 0.f, st_q0 = 0.f, st_q1 = 0.f;
    for (int r = warp; r < rows; r += nw) {
        size_t o = (size_t)r * 64 + c;
        float2 hv = *(const float2*)(h + o);
        float2 ah = *(const float2*)(g_Ah + o);
        float2 ss = *(const float2*)(g_ss + o);
        float2 ssh = *(const float2*)(g_ssh + o);
        float v0 = hv.x + ah.x + ssh.x / (ss.x + 1e-10f);
        float v1 = hv.y + ah.y + ssh.y / (ss.y + 1e-10f);
        *(float2*)(g_h2 + o) = make_float2(v0, v1);
        st_s0 += v0; st_q0 += v0 * v0;
        st_s1 += v1; st_q1 += v1 * v1;
    }
    atomicAdd(&g_stats[2 * 128 + c], st_s0);
    atomicAdd(&g_stats[2 * 128 + c + 1], st_s1);
    atomicAdd(&g_stats[2 * 128 + 64 + c], st_q0);
    atomicAdd(&g_stats[2 * 128 + 64 + c + 1], st_q1);
}

// ---------------- FFN: out = x2 + relu(bn(x2)@W1+b1)@W2 + b2 -------------------
// warp processes 4 rows at a time; x and z broadcast via per-warp smem buffer.
__global__ __launch_bounds__(256) void k_ffn(
    int which,  // 0: x2 = g_h2, 1: x2 = g_e2
    const float* __restrict__ W1, const float* __restrict__ b1,
    const float* __restrict__ W2, const float* __restrict__ b2,
    int rows, int set, float* __restrict__ out) {
    extern __shared__ float smd[];
    float* w1s = smd;              // 64*128
    float* w2s = smd + 8192;       // 128*64
    float* b1s = smd + 16384;      // 128
    float* buf = smd + 16512 + (threadIdx.x >> 5) * 512;  // per-warp 4 x 128
    for (int i = threadIdx.x; i < 8192; i += blockDim.x) { w1s[i] = W1[i]; w2s[i] = W2[i]; }
    if (threadIdx.x < 128) b1s[threadIdx.x] = b1[threadIdx.x];
    __syncthreads();

    const float* __restrict__ x2 = which ? g_e2 : g_h2;
    int lane = threadIdx.x & 31;
    int warp = (blockIdx.x * blockDim.x + threadIdx.x) >> 5;
    int nw = (gridDim.x * blockDim.x) >> 5;
    int c2 = lane * 2, c4 = lane * 4;
    float2 sc = *(const float2*)(g_scale + set * 64 + c2);
    float2 sh = *(const float2*)(g_shift + set * 64 + c2);
    float2 bo = *(const float2*)(b2 + c2);
    float4 b1v = *(const float4*)(b1s + c4);
    int ngroups = (rows + 3) >> 2;
    for (int g = warp; g < ngroups; g += nw) {
        int rbase = g * 4;
        float2 raw[4];
#pragma unroll
        for (int r = 0; r < 4; r++) {
            int row = rbase + r; if (row >= rows) row = rows - 1;
            float2 v = *(const float2*)(x2 + (size_t)row * 64 + c2);
            raw[r] = v;
            *(float2*)(buf + r * 128 + c2) = make_float2(v.x * sc.x + sh.x, v.y * sc.y + sh.y);
        }
        __syncwarp();
        // layer 1: lane owns hidden units [4*lane, 4*lane+4) for all 4 rows
        float a[4][4];
#pragma unroll
        for (int r = 0; r < 4; r++) { a[r][0] = b1v.x; a[r][1] = b1v.y; a[r][2] = b1v.z; a[r][3] = b1v.w; }
#pragma unroll 4
        for (int s = 0; s < 32; s++) {
            float4 wa = *(float4*)(w1s + (2 * s) * 128 + c4);
            float4 wb = *(float4*)(w1s + (2 * s + 1) * 128 + c4);
#pragma unroll
            for (int r = 0; r < 4; r++) {
                float2 xv = *(float2*)(buf + r * 128 + 2 * s);  // broadcast
                a[r][0] += xv.x * wa.x + xv.y * wb.x;
                a[r][1] += xv.x * wa.y + xv.y * wb.y;
                a[r][2] += xv.x * wa.z + xv.y * wb.z;
                a[r][3] += xv.x * wa.w + xv.y * wb.w;
            }
        }
        __syncwarp();  // all x reads done before z overwrites buf
#pragma unroll
        for (int r = 0; r < 4; r++) {
            *(float4*)(buf + r * 128 + c4) = make_float4(
                fmaxf(a[r][0], 0.f), fmaxf(a[r][1], 0.f),
                fmaxf(a[r][2], 0.f), fmaxf(a[r][3], 0.f));
        }
        __syncwarp();
        // layer 2: lane owns output cols [2*lane, 2*lane+2)
        float2 o[4] = {bo, bo, bo, bo};
#pragma unroll 4
        for (int s = 0; s < 32; s++) {
            float2 w0 = *(float2*)(w2s + (4 * s + 0) * 64 + c2);
            float2 w1v = *(float2*)(w2s + (4 * s + 1) * 64 + c2);
            float2 w2v = *(float2*)(w2s + (4 * s + 2) * 64 + c2);
            float2 w3 = *(float2*)(w2s + (4 * s + 3) * 64 + c2);
#pragma unroll
            for (int r = 0; r < 4; r++) {
                float4 zv = *(float4*)(buf + r * 128 + 4 * s);  // broadcast
                o[r].x += zv.x * w0.x + zv.y * w1v.x + zv.z * w2v.x + zv.w * w3.x;
                o[r].y += zv.x * w0.y + zv.y * w1v.y + zv.z * w2v.y + zv.w * w3.y;
            }
        }
        __syncwarp();  // z reads done before next group's x staging
#pragma unroll
        for (int r = 0; r < 4; r++) {
            int row = rbase + r;
            if (row < rows)
                *(float2*)(out + (size_t)row * 64 + c2) =
                    make_float2(raw[r].x + o[r].x, raw[r].y + o[r].y);
        }
    }
}

// ---------------- host launcher -------------------------------------------------
extern "C" void kernel_launch(void* const* d_in, const int* in_sizes, int n_in,
                              void* d_out, int out_size) {
    // Resolve input ordering: dict order has Ab (64 elems) at index 5,
    // signature order has Bw (4096 elems) there.
    int xAw, xAb, xBw, xBb, xCw, xCb, xDw, xDb, xEw, xEb;
    if (in_sizes[5] == 64) {  // dict order: Aw,Ab,Bw,Bb,Cw,Cb,Dw,Db,Ew,Eb
        xAw = 4; xAb = 5; xBw = 6; xBb = 7; xCw = 8; xCb = 9;
        xDw = 10; xDb = 11; xEw = 12; xEb = 13;
    } else {                  // signature order: Aw,Bw,Cw,Dw,Ew,Ab,Bb,Cb,Db,Eb
        xAw = 4; xBw = 5; xCw = 6; xDw = 7; xEw = 8;
        xAb = 9; xBb = 10; xCb = 11; xDb = 12; xEb = 13;
    }
    const float* h   = (const float*)d_in[0];
    const float* e   = (const float*)d_in[1];
    const int*   src = (const int*)d_in[2];
    const int*   dst = (const int*)d_in[3];
    const float* Aw = (const float*)d_in[xAw]; const float* Ab = (const float*)d_in[xAb];
    const float* Bw = (const float*)d_in[xBw]; const float* Bb = (const float*)d_in[xBb];
    const float* Cw = (const float*)d_in[xCw]; const float* Cb = (const float*)d_in[xCb];
    const float* Dw = (const float*)d_in[xDw]; const float* Db = (const float*)d_in[xDb];
    const float* Ew = (const float*)d_in[xEw]; const float* Eb = (const float*)d_in[xEb];
    const float* g1h = (const float*)d_in[14]; const float* g1e = (const float*)d_in[15];
    const float* g2h = (const float*)d_in[16]; const float* g2e = (const float*)d_in[17];
    const float* b1h = (const float*)d_in[18]; const float* b1e = (const float*)d_in[19];
    const float* b2h = (const float*)d_in[20]; const float* b2e = (const float*)d_in[21];
    const float* Wh1 = (const float*)d_in[22]; const float* bh1 = (const float*)d_in[23];
    const float* Wh2 = (const float*)d_in[24]; const float* bh2 = (const float*)d_in[25];
    const float* We1 = (const float*)d_in[26]; const float* be1 = (const float*)d_in[27];
    const float* We2 = (const float*)d_in[28]; const float* be2 = (const float*)d_in[29];
    float* out = (float*)d_out;

    int N = in_sizes[0] / 64;
    int E = in_sizes[2];

    cudaFuncSetAttribute(k_node, cudaFuncAttributeMaxDynamicSharedMemorySize, 65536);
    cudaFuncSetAttribute(k_ffn, cudaFuncAttributeMaxDynamicSharedMemorySize, 82432);

    k_zero<<<2048, 256>>>(N * 64);
    k_stats<<<512, 256>>>(h, N, 0);
    k_stats<<<2048, 256>>>(e, E, 1);
    k_finalize<<<1, 64>>>(0, g1h, b1h, 1.0f / (float)N);
    k_finalize<<<1, 64>>>(1, g1e, b1e, 1.0f / (float)E);
    k_node<<<444, 256, 65536>>>(h, Aw, Bw, Cw, Dw, Ab, Bb, Cb, Db, N);
    k_edge<<<1184, 256>>>(e, src, dst, Ew, Eb, E);
    k_h2<<<512, 256>>>(h, N);
    k_finalize<<<1, 64>>>(2, g2h, b2h, 1.0f / (float)N);
    k_finalize<<<1, 64>>>(3, g2e, b2e, 1.0f / (float)E);
    k_ffn<<<296, 256, 82432>>>(0, Wh1, bh1, Wh2, bh2, N, 2, out);
    k_ffn<<<296, 256, 82432>>>(1, We1, be1, We2, be2, E, 3, out + (size_t)N * 64);
}

// round 3
// speedup vs baseline: 1.8400x; 1.8400x over previous
#include <cuda_runtime.h>
#include <cuda_fp16.h>
#include <cstdint>

#define FULLMASK 0xffffffffu

// Problem sizes (fixed by the dataset)
#define CN 50000
#define CE 800000

// ---------------- scratch (device globals; no cudaMalloc allowed) -------------
__device__ float g_Ah[CN * 64];
__device__ float g_Bh[CN * 64];
__device__ float g_Ch[CN * 64];
__device__ float g_Dh[CN * 64];
__device__ float g_h2[CN * 64];
__device__ float g_ss[CN * 64];    // sum_sigma
__device__ float g_ssh[CN * 64];   // sum_sigma_h
__device__ float g_e2[CE * 64];    // e after residual (input to FFN-e)
__device__ float g_stats[4 * 128]; // [set][sum(64) | sumsq(64)]
__device__ float g_scale[4 * 64];  // folded BN: y = x*scale + shift
__device__ float g_shift[4 * 64];

// ================= mma.sync / ldmatrix helpers (base sm_103 ISA) ===============
__device__ __forceinline__ uint32_t smem_u32(const void* p) {
    return (uint32_t)__cvta_generic_to_shared(p);
}

__device__ __forceinline__ void ldsm_x4(uint32_t (&r)[4], uint32_t addr) {
    asm volatile("ldmatrix.sync.aligned.m8n8.x4.shared.b16 {%0,%1,%2,%3}, [%4];"
                 : "=r"(r[0]), "=r"(r[1]), "=r"(r[2]), "=r"(r[3]) : "r"(addr));
}

__device__ __forceinline__ void ldsm_x2t(uint32_t& b0, uint32_t& b1, uint32_t addr) {
    asm volatile("ldmatrix.sync.aligned.m8n8.x2.trans.shared.b16 {%0,%1}, [%2];"
                 : "=r"(b0), "=r"(b1) : "r"(addr));
}

__device__ __forceinline__ void mma_16816(float (&c)[4], const uint32_t (&a)[4],
                                          uint32_t b0, uint32_t b1) {
    asm volatile(
        "mma.sync.aligned.m16n8k16.row.col.f32.f16.f16.f32 "
        "{%0,%1,%2,%3}, {%4,%5,%6,%7}, {%8,%9}, {%0,%1,%2,%3};"
        : "+f"(c[0]), "+f"(c[1]), "+f"(c[2]), "+f"(c[3])
        : "r"(a[0]), "r"(a[1]), "r"(a[2]), "r"(a[3]), "r"(b0), "r"(b1));
}

// ---------------- zero scratch that is accumulated into -----------------------
__global__ void k_zero(int node_elems) {
    int i = blockIdx.x * blockDim.x + threadIdx.x;
    int stride = gridDim.x * blockDim.x;
    for (int j = i; j < node_elems; j += stride) {
        g_ss[j] = 0.f;
        g_ssh[j] = 0.f;
    }
    if (i < 4 * 128) g_stats[i] = 0.f;
}

// ---------------- column mean/var stats (sum + sumsq) -------------------------
__global__ __launch_bounds__(256) void k_stats(const float* __restrict__ x, int rows, int set) {
    __shared__ float ssum[64], ssq[64];
    int tid = threadIdx.x;
    if (tid < 64) { ssum[tid] = 0.f; ssq[tid] = 0.f; }
    __syncthreads();
    int cg = tid & 15;                                  // column group (4 cols)
    int r = (blockIdx.x * blockDim.x + tid) >> 4;
    int rstride = (gridDim.x * blockDim.x) >> 4;
    float4 s = make_float4(0, 0, 0, 0), q = make_float4(0, 0, 0, 0);
    for (; r < rows; r += rstride) {
        float4 v = *(const float4*)(x + (size_t)r * 64 + cg * 4);
        s.x += v.x; s.y += v.y; s.z += v.z; s.w += v.w;
        q.x += v.x * v.x; q.y += v.y * v.y; q.z += v.z * v.z; q.w += v.w * v.w;
    }
    atomicAdd(&ssum[cg * 4 + 0], s.x); atomicAdd(&ssum[cg * 4 + 1], s.y);
    atomicAdd(&ssum[cg * 4 + 2], s.z); atomicAdd(&ssum[cg * 4 + 3], s.w);
    atomicAdd(&ssq[cg * 4 + 0], q.x);  atomicAdd(&ssq[cg * 4 + 1], q.y);
    atomicAdd(&ssq[cg * 4 + 2], q.z);  atomicAdd(&ssq[cg * 4 + 3], q.w);
    __syncthreads();
    if (tid < 64) {
        atomicAdd(&g_stats[set * 128 + tid], ssum[tid]);
        atomicAdd(&g_stats[set * 128 + 64 + tid], ssq[tid]);
    }
}

// ---------------- fold BN into scale/shift -------------------------------------
__global__ void k_finalize(int set, const float* __restrict__ gamma,
                           const float* __restrict__ beta, float inv_count) {
    int t = threadIdx.x;  // 64 threads
    float mean = g_stats[set * 128 + t] * inv_count;
    float var = g_stats[set * 128 + 64 + t] * inv_count - mean * mean;
    float sc = gamma[t] * rsqrtf(var + 1e-5f);
    g_scale[set * 64 + t] = sc;
    g_shift[set * 64 + t] = beta[t] - mean * sc;
}

// ---------------- node linears: Ah,Bh,Ch,Dh = bn1(h) @ {A,B,C,D}w + b ---------
__global__ __launch_bounds__(256) void k_node(
    const float* __restrict__ h,
    const float* __restrict__ Aw, const float* __restrict__ Bw,
    const float* __restrict__ Cw, const float* __restrict__ Dw,
    const float* __restrict__ Ab, const float* __restrict__ Bb,
    const float* __restrict__ Cb, const float* __restrict__ Db,
    int rows) {
    extern __shared__ float sw[];  // 4 * 64*64
    for (int i = threadIdx.x; i < 4096; i += blockDim.x) {
        sw[i] = Aw[i]; sw[4096 + i] = Bw[i]; sw[8192 + i] = Cw[i]; sw[12288 + i] = Dw[i];
    }
    __syncthreads();
    int lane = threadIdx.x & 31;
    int warp = (blockIdx.x * blockDim.x + threadIdx.x) >> 5;
    int nw = (gridDim.x * blockDim.x) >> 5;
    int c = lane * 2;
    float2 sc = *(const float2*)(g_scale + c);       // set 0
    float2 sh = *(const float2*)(g_shift + c);
    float2 ab = *(const float2*)(Ab + c);
    float2 bb = *(const float2*)(Bb + c);
    float2 cb = *(const float2*)(Cb + c);
    float2 db = *(const float2*)(Db + c);
    for (int r = warp; r < rows; r += nw) {
        float2 hv = *(const float2*)(h + (size_t)r * 64 + c);
        float x0 = hv.x * sc.x + sh.x;
        float x1 = hv.y * sc.y + sh.y;
        float2 aA = ab, aB = bb, aC = cb, aD = db;
#pragma unroll 4
        for (int s = 0; s < 32; s++) {
            float xa = __shfl_sync(FULLMASK, x0, s);
            float xb = __shfl_sync(FULLMASK, x1, s);
            int k0 = (2 * s) * 64 + c, k1 = (2 * s + 1) * 64 + c;
            float2 wa, wb;
            wa = *(float2*)(sw + k0); wb = *(float2*)(sw + k1);
            aA.x += xa * wa.x + xb * wb.x; aA.y += xa * wa.y + xb * wb.y;
            wa = *(float2*)(sw + 4096 + k0); wb = *(float2*)(sw + 4096 + k1);
            aB.x += xa * wa.x + xb * wb.x; aB.y += xa * wa.y + xb * wb.y;
            wa = *(float2*)(sw + 8192 + k0); wb = *(float2*)(sw + 8192 + k1);
            aC.x += xa * wa.x + xb * wb.x; aC.y += xa * wa.y + xb * wb.y;
            wa = *(float2*)(sw + 12288 + k0); wb = *(float2*)(sw + 12288 + k1);
            aD.x += xa * wa.x + xb * wb.x; aD.y += xa * wa.y + xb * wb.y;
        }
        size_t o = (size_t)r * 64 + c;
        *(float2*)(g_Ah + o) = aA;
        *(float2*)(g_Bh + o) = aB;
        *(float2*)(g_Ch + o) = aC;
        *(float2*)(g_Dh + o) = aD;
    }
}

// ---------------- edge kernel: e_new, sigma, segment sums, e2 + its stats ------
__global__ __launch_bounds__(256) void k_edge(
    const float* __restrict__ e, const int* __restrict__ src, const int* __restrict__ dst,
    const float* __restrict__ Ew, const float* __restrict__ Eb, int ecount) {
    __shared__ float sm[4096 + 8 * 256];  // Ew + per-warp x staging (4 rows x 64)
    float* sw = sm;
    float* xs = sm + 4096 + (threadIdx.x >> 5) * 256;
    for (int i = threadIdx.x; i < 4096; i += blockDim.x) sw[i] = Ew[i];
    __syncthreads();
    int lane = threadIdx.x & 31;
    int warp = (blockIdx.x * blockDim.x + threadIdx.x) >> 5;
    int nw = (gridDim.x * blockDim.x) >> 5;
    int c = lane * 2;
    float2 sc = *(const float2*)(g_scale + 64 + c);  // set 1 (e)
    float2 sh = *(const float2*)(g_shift + 64 + c);
    float2 eb = *(const float2*)(Eb + c);
    float st_s0 = 0.f, st_s1 = 0.f, st_q0 = 0.f, st_q1 = 0.f;
    int ngroups = ecount >> 2;  // E divisible by 4
    for (int g = warp; g < ngroups; g += nw) {
        int ebase = g * 4;
        float2 raw[4];
#pragma unroll
        for (int r = 0; r < 4; r++) {
            float2 ev = *(const float2*)(e + (size_t)(ebase + r) * 64 + c);
            raw[r] = ev;
            *(float2*)(xs + r * 64 + c) = make_float2(ev.x * sc.x + sh.x, ev.y * sc.y + sh.y);
        }
        __syncwarp();
        float2 acc[4] = {eb, eb, eb, eb};
#pragma unroll 4
        for (int s = 0; s < 32; s++) {
            float2 wa = *(float2*)(sw + (2 * s) * 64 + c);
            float2 wb = *(float2*)(sw + (2 * s + 1) * 64 + c);
#pragma unroll
            for (int r = 0; r < 4; r++) {
                float2 xv = *(float2*)(xs + r * 64 + 2 * s);   // broadcast
                acc[r].x += xv.x * wa.x + xv.y * wb.x;
                acc[r].y += xv.x * wa.y + xv.y * wb.y;
            }
        }
        __syncwarp();
#pragma unroll
        for (int r = 0; r < 4; r++) {
            int eidx = ebase + r;
            int sI = src[eidx], dI = dst[eidx];
            float2 ch = *(const float2*)(g_Ch + (size_t)sI * 64 + c);
            float2 dh = *(const float2*)(g_Dh + (size_t)dI * 64 + c);
            float en0 = acc[r].x + ch.x + dh.x;
            float en1 = acc[r].y + ch.y + dh.y;
            float e20 = raw[r].x + en0, e21 = raw[r].y + en1;
            *(float2*)(g_e2 + (size_t)eidx * 64 + c) = make_float2(e20, e21);
            st_s0 += e20; st_q0 += e20 * e20;
            st_s1 += e21; st_q1 += e21 * e21;
            float sg0 = 1.f / (1.f + __expf(-en0));
            float sg1 = 1.f / (1.f + __expf(-en1));
            float2 bh = *(const float2*)(g_Bh + (size_t)sI * 64 + c);
            size_t o = (size_t)dI * 64 + c;
            atomicAdd((float2*)(g_ss + o), make_float2(sg0, sg1));
            atomicAdd((float2*)(g_ssh + o), make_float2(bh.x * sg0, bh.y * sg1));
        }
    }
    // e2 stats -> set 3
    atomicAdd(&g_stats[3 * 128 + c], st_s0);
    atomicAdd(&g_stats[3 * 128 + c + 1], st_s1);
    atomicAdd(&g_stats[3 * 128 + 64 + c], st_q0);
    atomicAdd(&g_stats[3 * 128 + 64 + c + 1], st_q1);
}

// ---------------- h2 = h + Ah + ssh/(ss+eps), plus its stats -------------------
__global__ __launch_bounds__(256) void k_h2(const float* __restrict__ h, int rows) {
    int lane = threadIdx.x & 31;
    int warp = (blockIdx.x * blockDim.x + threadIdx.x) >> 5;
    int nw = (gridDim.x * blockDim.x) >> 5;
    int c = lane * 2;
    float st_s0 = 0.f, st_s1 = 0.f, st_q0 = 0.f, st_q1 = 0.f;
    for (int r = warp; r < rows; r += nw) {
        size_t o = (size_t)r * 64 + c;
        float2 hv = *(const float2*)(h + o);
        float2 ah = *(const float2*)(g_Ah + o);
        float2 ss = *(const float2*)(g_ss + o);
        float2 ssh = *(const float2*)(g_ssh + o);
        float v0 = hv.x + ah.x + ssh.x / (ss.x + 1e-10f);
        float v1 = hv.y + ah.y + ssh.y / (ss.y + 1e-10f);
        *(float2*)(g_h2 + o) = make_float2(v0, v1);
        st_s0 += v0; st_q0 += v0 * v0;
        st_s1 += v1; st_q1 += v1 * v1;
    }
    atomicAdd(&g_stats[2 * 128 + c], st_s0);
    atomicAdd(&g_stats[2 * 128 + c + 1], st_s1);
    atomicAdd(&g_stats[2 * 128 + 64 + c], st_q0);
    atomicAdd(&g_stats[2 * 128 + 64 + c + 1], st_q1);
}

// ---------------- FFN via mma.sync: out = x2 + relu(bn(x2)@W1+b1)@W2 + b2 ------
// 128 threads = 4 warps per CTA; each warp independently processes 16-row groups.
// GEMM1: [16,64]@[64,128] (A ldmatrix.x4, B ldmatrix.x2.trans)
// GEMM1 C frags repack in-register (bias+relu+fp16) into GEMM2 A frags.
// GEMM2: [16,128]@[128,64].
__global__ void __launch_bounds__(128) k_ffn_mma(
    int which,  // 0: x2 = g_h2, 1: x2 = g_e2
    const float* __restrict__ W1, const float* __restrict__ b1,
    const float* __restrict__ W2, const float* __restrict__ b2,
    int rows, int set, float* __restrict__ out) {
    const int LDA = 72, LDB1 = 136, LDB2 = 72;
    __shared__ __half sB1[64 * 136];   // W1 [k][n] row-major, padded
    __shared__ __half sB2[128 * 72];   // W2 [k][n] row-major, padded
    __shared__ __half sA[4][16 * 72];  // per-warp X stripe fp16
    __shared__ float sb1[128], sb2[64];

    int tid = threadIdx.x, wid = tid >> 5, lane = tid & 31;

    for (int i = tid; i < 64 * 128; i += 128) {
        int r = i >> 7, c = i & 127;
        sB1[r * LDB1 + c] = __float2half(W1[i]);
    }
    for (int i = tid; i < 128 * 64; i += 128) {
        int r = i >> 6, c = i & 63;
        sB2[r * LDB2 + c] = __float2half(W2[i]);
    }
    if (tid < 128) sb1[tid] = b1[tid];
    if (tid < 64)  sb2[tid] = b2[tid];
    __syncthreads();

    const float* __restrict__ xsrc = which ? g_e2 : g_h2;
    uint32_t aU = smem_u32(&sA[wid][0]);
    uint32_t b1U = smem_u32(sB1);
    uint32_t b2U = smem_u32(sB2);

    int cg = lane & 15;
    float4 sc4 = *(const float4*)(g_scale + set * 64 + cg * 4);
    float4 sh4 = *(const float4*)(g_shift + set * 64 + cg * 4);

    // ldmatrix source addresses (fixed per lane)
    uint32_t aLdAddr = aU + (uint32_t)(((lane & 15) * LDA + ((lane >> 4) << 3)) * 2);
    uint32_t bRow = (uint32_t)(lane & 15);  // k row within 16-k tile

    int ngroups = (rows + 15) >> 4;
    int gw = blockIdx.x * 4 + wid;
    int gstride = gridDim.x * 4;
    for (int g = gw; g < ngroups; g += gstride) {
        int rbase = g << 4;
        // ---- stage 16 x 64 fp16 tile (bn folded) into this warp's buffer ----
        int rsub = lane >> 4;
#pragma unroll
        for (int j = 0; j < 8; j++) {
            int rloc = rsub + j * 2;
            int row = rbase + rloc; if (row >= rows) row = rows - 1;
            float4 v = *(const float4*)(xsrc + (size_t)row * 64 + cg * 4);
            __half2 h0 = __floats2half2_rn(v.x * sc4.x + sh4.x, v.y * sc4.y + sh4.y);
            __half2 h1 = __floats2half2_rn(v.z * sc4.z + sh4.z, v.w * sc4.w + sh4.w);
            __half* dstp = &sA[wid][rloc * LDA + cg * 4];
            *(__half2*)(dstp) = h0;
            *(__half2*)(dstp + 2) = h1;
        }
        __syncwarp();

        // ---- GEMM1: A frags for all 4 k-tiles ----
        uint32_t afr[4][4];
#pragma unroll
        for (int kt = 0; kt < 4; kt++)
            ldsm_x4(afr[kt], aLdAddr + (uint32_t)(kt * 16 * 2));

        float c1[16][4];
#pragma unroll
        for (int nt = 0; nt < 16; nt++) {
            c1[nt][0] = 0.f; c1[nt][1] = 0.f; c1[nt][2] = 0.f; c1[nt][3] = 0.f;
#pragma unroll
            for (int kt = 0; kt < 4; kt++) {
                uint32_t b0, bq;
                uint32_t addr = b1U + (uint32_t)((((kt * 16) + bRow) * LDB1 + nt * 8) * 2);
                ldsm_x2t(b0, bq, addr);
                mma_16816(c1[nt], afr[kt], b0, bq);
            }
        }

        // ---- epilogue1: bias + relu + pack -> GEMM2 A frags ----
        uint32_t a2[8][4];
#pragma unroll
        for (int nt = 0; nt < 16; nt++) {
            int n0 = nt * 8 + 2 * (lane & 3);
            float bx = sb1[n0], by = sb1[n0 + 1];
            __half2 lo = __floats2half2_rn(fmaxf(c1[nt][0] + bx, 0.f),
                                           fmaxf(c1[nt][1] + by, 0.f));
            __half2 hi = __floats2half2_rn(fmaxf(c1[nt][2] + bx, 0.f),
                                           fmaxf(c1[nt][3] + by, 0.f));
            int kt2 = nt >> 1, base = (nt & 1) * 2;
            a2[kt2][base]     = *reinterpret_cast<uint32_t*>(&lo);
            a2[kt2][base + 1] = *reinterpret_cast<uint32_t*>(&hi);
        }

        // ---- GEMM2 ----
        float c2[8][4];
#pragma unroll
        for (int nt = 0; nt < 8; nt++) {
            c2[nt][0] = 0.f; c2[nt][1] = 0.f; c2[nt][2] = 0.f; c2[nt][3] = 0.f;
#pragma unroll
            for (int kt = 0; kt < 8; kt++) {
                uint32_t b0, bq;
                uint32_t addr = b2U + (uint32_t)((((kt * 16) + bRow) * LDB2 + nt * 8) * 2);
                ldsm_x2t(b0, bq, addr);
                mma_16816(c2[nt], a2[kt], b0, bq);
            }
        }

        // ---- epilogue2: residual + bias2, store ----
        int r0 = rbase + (lane >> 2);
        int r1 = r0 + 8;
#pragma unroll
        for (int nt = 0; nt < 8; nt++) {
            int n = nt * 8 + 2 * (lane & 3);
            float bx = sb2[n], by = sb2[n + 1];
            if (r0 < rows) {
                float2 xv = *(const float2*)(xsrc + (size_t)r0 * 64 + n);
                *(float2*)(out + (size_t)r0 * 64 + n) =
                    make_float2(xv.x + bx + c2[nt][0], xv.y + by + c2[nt][1]);
            }
            if (r1 < rows) {
                float2 xv = *(const float2*)(xsrc + (size_t)r1 * 64 + n);
                *(float2*)(out + (size_t)r1 * 64 + n) =
                    make_float2(xv.x + bx + c2[nt][2], xv.y + by + c2[nt][3]);
            }
        }
        __syncwarp();
    }
}

// ---------------- host launcher -------------------------------------------------
extern "C" void kernel_launch(void* const* d_in, const int* in_sizes, int n_in,
                              void* d_out, int out_size) {
    int xAw, xAb, xBw, xBb, xCw, xCb, xDw, xDb, xEw, xEb;
    if (in_sizes[5] == 64) {  // dict order: Aw,Ab,Bw,Bb,Cw,Cb,Dw,Db,Ew,Eb
        xAw = 4; xAb = 5; xBw = 6; xBb = 7; xCw = 8; xCb = 9;
        xDw = 10; xDb = 11; xEw = 12; xEb = 13;
    } else {                  // signature order: Aw,Bw,Cw,Dw,Ew,Ab,Bb,Cb,Db,Eb
        xAw = 4; xBw = 5; xCw = 6; xDw = 7; xEw = 8;
        xAb = 9; xBb = 10; xCb = 11; xDb = 12; xEb = 13;
    }
    const float* h   = (const float*)d_in[0];
    const float* e   = (const float*)d_in[1];
    const int*   src = (const int*)d_in[2];
    const int*   dst = (const int*)d_in[3];
    const float* Aw = (const float*)d_in[xAw]; const float* Ab = (const float*)d_in[xAb];
    const float* Bw = (const float*)d_in[xBw]; const float* Bb = (const float*)d_in[xBb];
    const float* Cw = (const float*)d_in[xCw]; const float* Cb = (const float*)d_in[xCb];
    const float* Dw = (const float*)d_in[xDw]; const float* Db = (const float*)d_in[xDb];
    const float* Ew = (const float*)d_in[xEw]; const float* Eb = (const float*)d_in[xEb];
    const float* g1h = (const float*)d_in[14]; const float* g1e = (const float*)d_in[15];
    const float* g2h = (const float*)d_in[16]; const float* g2e = (const float*)d_in[17];
    const float* b1h = (const float*)d_in[18]; const float* b1e = (const float*)d_in[19];
    const float* b2h = (const float*)d_in[20]; const float* b2e = (const float*)d_in[21];
    const float* Wh1 = (const float*)d_in[22]; const float* bh1 = (const float*)d_in[23];
    const float* Wh2 = (const float*)d_in[24]; const float* bh2 = (const float*)d_in[25];
    const float* We1 = (const float*)d_in[26]; const float* be1 = (const float*)d_in[27];
    const float* We2 = (const float*)d_in[28]; const float* be2 = (const float*)d_in[29];
    float* out = (float*)d_out;

    int N = in_sizes[0] / 64;
    int E = in_sizes[2];

    cudaFuncSetAttribute(k_node, cudaFuncAttributeMaxDynamicSharedMemorySize, 65536);

    k_zero<<<2048, 256>>>(N * 64);
    k_stats<<<512, 256>>>(h, N, 0);
    k_stats<<<2048, 256>>>(e, E, 1);
    k_finalize<<<1, 64>>>(0, g1h, b1h, 1.0f / (float)N);
    k_finalize<<<1, 64>>>(1, g1e, b1e, 1.0f / (float)E);
    k_node<<<444, 256, 65536>>>(h, Aw, Bw, Cw, Dw, Ab, Bb, Cb, Db, N);
    k_edge<<<1184, 256>>>(e, src, dst, Ew, Eb, E);
    k_h2<<<512, 256>>>(h, N);
    k_finalize<<<1, 64>>>(2, g2h, b2h, 1.0f / (float)N);
    k_finalize<<<1, 64>>>(3, g2e, b2e, 1.0f / (float)E);
    k_ffn_mma<<<592, 128>>>(0, Wh1, bh1, Wh2, bh2, N, 2, out);
    k_ffn_mma<<<592, 128>>>(1, We1, be1, We2, be2, E, 3, out + (size_t)N * 64);
}

// round 4
// speedup vs baseline: 1.8920x; 1.0282x over previous
#include <cuda_runtime.h>
#include <cuda_fp16.h>
#include <cstdint>

#define FULLMASK 0xffffffffu

// Problem sizes (fixed by the dataset)
#define CN 50000
#define CE 800000

// ---------------- scratch (device globals; no cudaMalloc allowed) -------------
__device__ __align__(16) float g_Ah[CN * 64];
__device__ __align__(16) float g_Bh[CN * 64];
__device__ __align__(16) float g_Ch[CN * 64];
__device__ __align__(16) float g_Dh[CN * 64];
__device__ __align__(16) float g_h2[CN * 64];
__device__ __align__(16) float g_ss[CN * 64];    // sum_sigma
__device__ __align__(16) float g_ssh[CN * 64];   // sum_sigma_h
__device__ __align__(16) float g_e2[CE * 64];    // e after residual (input to FFN-e)
__device__ float g_stats[4 * 128]; // [set][sum(64) | sumsq(64)]
__device__ float g_scale[4 * 64];  // folded BN: y = x*scale + shift
__device__ float g_shift[4 * 64];
// folded fp16 weights: slots 0-3 = A,B,C,D (64x64); 4 = E (64x64); 5,6 = W1h,W1e (64x128)
__device__ __half g_fw[7 * 64 * 128];
__device__ float g_fb[7 * 128];

// ================= mma.sync / ldmatrix helpers (base sm_103 ISA) ===============
__device__ __forceinline__ uint32_t smem_u32(const void* p) {
    return (uint32_t)__cvta_generic_to_shared(p);
}

__device__ __forceinline__ void ldsm_x4(uint32_t (&r)[4], uint32_t addr) {
    asm volatile("ldmatrix.sync.aligned.m8n8.x4.shared.b16 {%0,%1,%2,%3}, [%4];"
                 : "=r"(r[0]), "=r"(r[1]), "=r"(r[2]), "=r"(r[3]) : "r"(addr));
}

__device__ __forceinline__ void ldsm_x2t(uint32_t& b0, uint32_t& b1, uint32_t addr) {
    asm volatile("ldmatrix.sync.aligned.m8n8.x2.trans.shared.b16 {%0,%1}, [%2];"
                 : "=r"(b0), "=r"(b1) : "r"(addr));
}

__device__ __forceinline__ void mma_16816(float (&c)[4], const uint32_t (&a)[4],
                                          uint32_t b0, uint32_t b1) {
    asm volatile(
        "mma.sync.aligned.m16n8k16.row.col.f32.f16.f16.f32 "
        "{%0,%1,%2,%3}, {%4,%5,%6,%7}, {%8,%9}, {%0,%1,%2,%3};"
        : "+f"(c[0]), "+f"(c[1]), "+f"(c[2]), "+f"(c[3])
        : "r"(a[0]), "r"(a[1]), "r"(a[2]), "r"(a[3]), "r"(b0), "r"(b1));
}

// ---------------- zero scratch that is accumulated into -----------------------
__global__ void k_zero(int node_elems) {
    int i = blockIdx.x * blockDim.x + threadIdx.x;
    int stride = gridDim.x * blockDim.x;
    for (int j = i; j < node_elems; j += stride) {
        g_ss[j] = 0.f;
        g_ssh[j] = 0.f;
    }
    if (i < 4 * 128) g_stats[i] = 0.f;
}

// ---------------- column mean/var stats (sum + sumsq) -------------------------
__global__ __launch_bounds__(256) void k_stats(const float* __restrict__ x, int rows, int set) {
    __shared__ float ssum[64], ssq[64];
    int tid = threadIdx.x;
    if (tid < 64) { ssum[tid] = 0.f; ssq[tid] = 0.f; }
    __syncthreads();
    int cg = tid & 15;                                  // column group (4 cols)
    int r = (blockIdx.x * blockDim.x + tid) >> 4;
    int rstride = (gridDim.x * blockDim.x) >> 4;
    float4 s = make_float4(0, 0, 0, 0), q = make_float4(0, 0, 0, 0);
    for (; r < rows; r += rstride) {
        float4 v = *(const float4*)(x + (size_t)r * 64 + cg * 4);
        s.x += v.x; s.y += v.y; s.z += v.z; s.w += v.w;
        q.x += v.x * v.x; q.y += v.y * v.y; q.z += v.z * v.z; q.w += v.w * v.w;
    }
    atomicAdd(&ssum[cg * 4 + 0], s.x); atomicAdd(&ssum[cg * 4 + 1], s.y);
    atomicAdd(&ssum[cg * 4 + 2], s.z); atomicAdd(&ssum[cg * 4 + 3], s.w);
    atomicAdd(&ssq[cg * 4 + 0], q.x);  atomicAdd(&ssq[cg * 4 + 1], q.y);
    atomicAdd(&ssq[cg * 4 + 2], q.z);  atomicAdd(&ssq[cg * 4 + 3], q.w);
    __syncthreads();
    if (tid < 64) {
        atomicAdd(&g_stats[set * 128 + tid], ssum[tid]);
        atomicAdd(&g_stats[set * 128 + 64 + tid], ssq[tid]);
    }
}

// ---------------- fold BN into scale/shift -------------------------------------
__global__ void k_finalize(int set, const float* __restrict__ gamma,
                           const float* __restrict__ beta, float inv_count) {
    int t = threadIdx.x;  // 64 threads
    float mean = g_stats[set * 128 + t] * inv_count;
    float var = g_stats[set * 128 + 64 + t] * inv_count - mean * mean;
    float sc = gamma[t] * rsqrtf(var + 1e-5f);
    g_scale[set * 64 + t] = sc;
    g_shift[set * 64 + t] = beta[t] - mean * sc;
}

// ---------------- fold BN into weights: W' = diag(sc)W (fp16), b' = b + sh@W ---
__global__ void k_fold5(const float* W0, const float* b0, const float* W1, const float* b1,
                        const float* W2, const float* b2, const float* W3, const float* b3,
                        const float* W4, const float* b4) {
    int m = blockIdx.x;  // 0..4 = A,B,C,D,E
    const float* W = m == 0 ? W0 : m == 1 ? W1 : m == 2 ? W2 : m == 3 ? W3 : W4;
    const float* bb = m == 0 ? b0 : m == 1 ? b1 : m == 2 ? b2 : m == 3 ? b3 : b4;
    int set = (m == 4) ? 1 : 0;
    int n = threadIdx.x;  // 64
    const float* sc = g_scale + set * 64;
    const float* sh = g_shift + set * 64;
    float acc = bb[n];
    __half* wo = g_fw + m * 64 * 128;
    for (int k = 0; k < 64; k++) {
        float w = W[k * 64 + n];
        acc += sh[k] * w;
        wo[k * 64 + n] = __float2half(sc[k] * w);
    }
    g_fb[m * 128 + n] = acc;
}

__global__ void k_fold2(const float* Wa, const float* ba, const float* Wb, const float* bbp) {
    int m = blockIdx.x;  // 0: h (set2, slot5); 1: e (set3, slot6)
    const float* W = m == 0 ? Wa : Wb;
    const float* bb = m == 0 ? ba : bbp;
    int set = 2 + m, slot = 5 + m;
    int n = threadIdx.x;  // 128
    const float* sc = g_scale + set * 64;
    const float* sh = g_shift + set * 64;
    float acc = bb[n];
    __half* wo = g_fw + slot * 64 * 128;
    for (int k = 0; k < 64; k++) {
        float w = W[k * 128 + n];
        acc += sh[k] * w;
        wo[k * 128 + n] = __float2half(sc[k] * w);
    }
    g_fb[slot * 128 + n] = acc;
}

// ---------------- node linears via mma: Ah..Dh = bn1(h)@{A..D}w + b ------------
// Combined [N,64] @ [64,256]; warp per 16-row tile; two 128-col passes.
__global__ __launch_bounds__(256) void k_node_mma(const float* __restrict__ h, int rows) {
    extern __shared__ __half smn[];
    __half* sW = smn;                      // [64][264] combined folded weights
    __half* sA = smn + 64 * 264;           // 8 warps x [16][72]
    for (int i = threadIdx.x; i < 64 * 256; i += 256) {
        int r = i >> 8, c = i & 255;
        sW[r * 264 + c] = g_fw[(c >> 6) * 64 * 128 + r * 64 + (c & 63)];
    }
    __syncthreads();
    int tid = threadIdx.x, wid = tid >> 5, lane = tid & 31;
    __half* aBuf = sA + wid * 16 * 72;
    uint32_t aU = smem_u32(aBuf);
    uint32_t wU = smem_u32(sW);
    uint32_t aLd = aU + (uint32_t)(((lane & 15) * 72 + ((lane >> 4) << 3)) * 2);
    uint32_t bRow = lane & 15;
    int cg = lane & 15, rsub = lane >> 4;
    int ntiles = (rows + 15) >> 4;
    for (int t = blockIdx.x * 8 + wid; t < ntiles; t += gridDim.x * 8) {
        int rbase = t << 4;
#pragma unroll
        for (int j = 0; j < 8; j++) {
            int rloc = rsub + j * 2;
            int row = rbase + rloc; if (row >= rows) row = rows - 1;
            float4 v = *(const float4*)(h + (size_t)row * 64 + cg * 4);
            __half* dp = aBuf + rloc * 72 + cg * 4;
            *(__half2*)dp = __floats2half2_rn(v.x, v.y);
            *(__half2*)(dp + 2) = __floats2half2_rn(v.z, v.w);
        }
        __syncwarp();
        uint32_t afr[4][4];
#pragma unroll
        for (int kt = 0; kt < 4; kt++) ldsm_x4(afr[kt], aLd + kt * 32);
        int r0 = rbase + (lane >> 2), r1 = r0 + 8;
#pragma unroll
        for (int p = 0; p < 2; p++) {
            float c[16][4];
#pragma unroll
            for (int nt = 0; nt < 16; nt++) {
                c[nt][0] = c[nt][1] = c[nt][2] = c[nt][3] = 0.f;
#pragma unroll
                for (int kt = 0; kt < 4; kt++) {
                    uint32_t b0, b1;
                    ldsm_x2t(b0, b1, wU + (uint32_t)(((kt * 16 + bRow) * 264 + p * 128 + nt * 8) * 2));
                    mma_16816(c[nt], afr[kt], b0, b1);
                }
            }
#pragma unroll
            for (int nt = 0; nt < 16; nt++) {
                int slot = p * 2 + (nt >> 3);
                int col = (nt & 7) * 8 + 2 * (lane & 3);
                float* op = slot == 0 ? g_Ah : slot == 1 ? g_Bh : slot == 2 ? g_Ch : g_Dh;
                float2 bia = *(const float2*)(g_fb + slot * 128 + col);
                if (r0 < rows)
                    *(float2*)(op + (size_t)r0 * 64 + col) =
                        make_float2(c[nt][0] + bia.x, c[nt][1] + bia.y);
                if (r1 < rows)
                    *(float2*)(op + (size_t)r1 * 64 + col) =
                        make_float2(c[nt][2] + bia.x, c[nt][3] + bia.y);
            }
        }
        __syncwarp();
    }
}

// ---------------- fused edge kernel: Ee GEMM + gates + segment sums ------------
// warp per 16 edges. e_new = e@Ew' + b' + Ch[src] + Dh[dst]; e2 = e + e_new;
// sigma = sigmoid(e_new); float4 vector atomics for segment sums; e2 stats.
__global__ void __launch_bounds__(256, 2) k_edge_mma(
    const float* __restrict__ e, const int* __restrict__ src, const int* __restrict__ dst,
    int ecount) {
    __shared__ __half sW[64 * 72];
    __shared__ __half sA[8][16 * 72];
    __shared__ float sst[128];
    int tid = threadIdx.x, wid = tid >> 5, lane = tid & 31;
    const __half* fw = g_fw + 4 * 64 * 128;
    for (int i = tid; i < 64 * 64; i += 256) { int r = i >> 6, c = i & 63; sW[r * 72 + c] = fw[i]; }
    if (tid < 128) sst[tid] = 0.f;
    __syncthreads();
    uint32_t aU = smem_u32(&sA[wid][0]);
    uint32_t wU = smem_u32(sW);
    uint32_t aLd = aU + (uint32_t)(((lane & 15) * 72 + ((lane >> 4) << 3)) * 2);
    uint32_t bRow = lane & 15;
    int cg = lane & 15, rsub = lane >> 4;
    float2 biasr[8];
#pragma unroll
    for (int nt = 0; nt < 8; nt++)
        biasr[nt] = *(const float2*)(g_fb + 4 * 128 + nt * 8 + 2 * (lane & 3));
    int colsel = ((lane & 3) >> 1) << 2;
    bool even = (lane & 1) == 0;
    float2 st_s[8], st_q[8];
#pragma unroll
    for (int i = 0; i < 8; i++) { st_s[i] = make_float2(0.f, 0.f); st_q[i] = make_float2(0.f, 0.f); }
    int ntiles = ecount >> 4;
    for (int t = blockIdx.x * 8 + wid; t < ntiles; t += gridDim.x * 8) {
        int ebase = t << 4;
#pragma unroll
        for (int j = 0; j < 8; j++) {
            int rloc = rsub + j * 2;
            float4 v = *(const float4*)(e + (size_t)(ebase + rloc) * 64 + cg * 4);
            __half* dp = &sA[wid][rloc * 72 + cg * 4];
            *(__half2*)dp = __floats2half2_rn(v.x, v.y);
            *(__half2*)(dp + 2) = __floats2half2_rn(v.z, v.w);
        }
        __syncwarp();
        uint32_t afr[4][4];
#pragma unroll
        for (int kt = 0; kt < 4; kt++) ldsm_x4(afr[kt], aLd + kt * 32);
        float c[8][4];
#pragma unroll
        for (int nt = 0; nt < 8; nt++) {
            c[nt][0] = c[nt][1] = c[nt][2] = c[nt][3] = 0.f;
#pragma unroll
            for (int kt = 0; kt < 4; kt++) {
                uint32_t b0, b1;
                ldsm_x2t(b0, b1, wU + (uint32_t)(((kt * 16 + bRow) * 72 + nt * 8) * 2));
                mma_16816(c[nt], afr[kt], b0, b1);
            }
        }
        int r0 = ebase + (lane >> 2), r1 = r0 + 8;
        int sI0 = src[r0], dI0 = dst[r0], sI1 = src[r1], dI1 = dst[r1];
        int drow = even ? dI0 : dI1;
#pragma unroll
        for (int nt = 0; nt < 8; nt++) {
            int c0 = nt * 8 + 2 * (lane & 3);
            float2 ch0 = *(const float2*)(g_Ch + (size_t)sI0 * 64 + c0);
            float2 dh0 = *(const float2*)(g_Dh + (size_t)dI0 * 64 + c0);
            float2 ch1 = *(const float2*)(g_Ch + (size_t)sI1 * 64 + c0);
            float2 dh1 = *(const float2*)(g_Dh + (size_t)dI1 * 64 + c0);
            float en00 = c[nt][0] + biasr[nt].x + ch0.x + dh0.x;
            float en01 = c[nt][1] + biasr[nt].y + ch0.y + dh0.y;
            float en10 = c[nt][2] + biasr[nt].x + ch1.x + dh1.x;
            float en11 = c[nt][3] + biasr[nt].y + ch1.y + dh1.y;
            float2 ev0 = *(const float2*)(e + (size_t)r0 * 64 + c0);
            float2 ev1 = *(const float2*)(e + (size_t)r1 * 64 + c0);
            float e200 = ev0.x + en00, e201 = ev0.y + en01;
            float e210 = ev1.x + en10, e211 = ev1.y + en11;
            *(float2*)(g_e2 + (size_t)r0 * 64 + c0) = make_float2(e200, e201);
            *(float2*)(g_e2 + (size_t)r1 * 64 + c0) = make_float2(e210, e211);
            st_s[nt].x += e200 + e210; st_s[nt].y += e201 + e211;
            st_q[nt].x += e200 * e200 + e210 * e210;
            st_q[nt].y += e201 * e201 + e211 * e211;
            float sg00 = 1.f / (1.f + __expf(-en00));
            float sg01 = 1.f / (1.f + __expf(-en01));
            float sg10 = 1.f / (1.f + __expf(-en10));
            float sg11 = 1.f / (1.f + __expf(-en11));
            float2 bh0 = *(const float2*)(g_Bh + (size_t)sI0 * 64 + c0);
            float2 bh1 = *(const float2*)(g_Bh + (size_t)sI1 * 64 + c0);
            float p00 = bh0.x * sg00, p01 = bh0.y * sg01;
            float p10 = bh1.x * sg10, p11 = bh1.y * sg11;
            // lane-pair shuffle -> float4 vector atomics (even lanes row r0, odd row r1)
            float o00 = __shfl_xor_sync(FULLMASK, sg00, 1), o01 = __shfl_xor_sync(FULLMASK, sg01, 1);
            float o10 = __shfl_xor_sync(FULLMASK, sg10, 1), o11 = __shfl_xor_sync(FULLMASK, sg11, 1);
            float4 sv = even ? make_float4(sg00, sg01, o00, o01)
                             : make_float4(o10, o11, sg10, sg11);
            atomicAdd((float4*)(g_ss + (size_t)drow * 64 + nt * 8 + colsel), sv);
            float q00 = __shfl_xor_sync(FULLMASK, p00, 1), q01 = __shfl_xor_sync(FULLMASK, p01, 1);
            float q10 = __shfl_xor_sync(FULLMASK, p10, 1), q11 = __shfl_xor_sync(FULLMASK, p11, 1);
            float4 pv = even ? make_float4(p00, p01, q00, q01)
                             : make_float4(q10, q11, p10, p11);
            atomicAdd((float4*)(g_ssh + (size_t)drow * 64 + nt * 8 + colsel), pv);
        }
        __syncwarp();
    }
    // e2 stats -> CTA smem -> global (set 3)
#pragma unroll
    for (int nt = 0; nt < 8; nt++) {
        int c0 = nt * 8 + 2 * (lane & 3);
        atomicAdd(&sst[c0], st_s[nt].x);
        atomicAdd(&sst[c0 + 1], st_s[nt].y);
        atomicAdd(&sst[64 + c0], st_q[nt].x);
        atomicAdd(&sst[64 + c0 + 1], st_q[nt].y);
    }
    __syncthreads();
    if (tid < 128) atomicAdd(&g_stats[3 * 128 + tid], sst[tid]);
}

// ---------------- h2 = h + Ah + ssh/(ss+eps), plus its stats -------------------
__global__ __launch_bounds__(256) void k_h2(const float* __restrict__ h, int rows) {
    int lane = threadIdx.x & 31;
    int warp = (blockIdx.x * blockDim.x + threadIdx.x) >> 5;
    int nw = (gridDim.x * blockDim.x) >> 5;
    int c = lane * 2;
    float st_s0 = 0.f, st_s1 = 0.f, st_q0 = 0.f, st_q1 = 0.f;
    for (int r = warp; r < rows; r += nw) {
        size_t o = (size_t)r * 64 + c;
        float2 hv = *(const float2*)(h + o);
        float2 ah = *(const float2*)(g_Ah + o);
        float2 ss = *(const float2*)(g_ss + o);
        float2 ssh = *(const float2*)(g_ssh + o);
        float v0 = hv.x + ah.x + ssh.x / (ss.x + 1e-10f);
        float v1 = hv.y + ah.y + ssh.y / (ss.y + 1e-10f);
        *(float2*)(g_h2 + o) = make_float2(v0, v1);
        st_s0 += v0; st_q0 += v0 * v0;
        st_s1 += v1; st_q1 += v1 * v1;
    }
    atomicAdd(&g_stats[2 * 128 + c], st_s0);
    atomicAdd(&g_stats[2 * 128 + c + 1], st_s1);
    atomicAdd(&g_stats[2 * 128 + 64 + c], st_q0);
    atomicAdd(&g_stats[2 * 128 + 64 + c + 1], st_q1);
}

// ---------------- FFN via mma.sync: out = x2 + relu(x2@W1'+b1')@W2 + b2 --------
__global__ void __launch_bounds__(128) k_ffn_mma(
    int which,  // 0: x2 = g_h2, 1: x2 = g_e2
    int slot,   // folded W1 slot (5 or 6)
    const float* __restrict__ W2, const float* __restrict__ b2,
    int rows, float* __restrict__ out) {
    const int LDA = 72, LDB1 = 136, LDB2 = 72;
    __shared__ __half sB1[64 * 136];   // folded W1 [k][n] padded
    __shared__ __half sB2[128 * 72];   // W2 [k][n] padded
    __shared__ __half sA[4][16 * 72];  // per-warp X stripe fp16
    __shared__ float sb1[128], sb2[64];

    int tid = threadIdx.x, wid = tid >> 5, lane = tid & 31;
    const __half* fw1 = g_fw + slot * 64 * 128;
    for (int i = tid; i < 64 * 128; i += 128) {
        int r = i >> 7, c = i & 127;
        sB1[r * LDB1 + c] = fw1[i];
    }
    for (int i = tid; i < 128 * 64; i += 128) {
        int r = i >> 6, c = i & 63;
        sB2[r * LDB2 + c] = __float2half(W2[i]);
    }
    if (tid < 128) sb1[tid] = g_fb[slot * 128 + tid];
    if (tid < 64)  sb2[tid] = b2[tid];
    __syncthreads();

    const float* __restrict__ xsrc = which ? g_e2 : g_h2;
    uint32_t aU = smem_u32(&sA[wid][0]);
    uint32_t b1U = smem_u32(sB1);
    uint32_t b2U = smem_u32(sB2);
    int cg = lane & 15;
    uint32_t aLdAddr = aU + (uint32_t)(((lane & 15) * LDA + ((lane >> 4) << 3)) * 2);
    uint32_t bRow = (uint32_t)(lane & 15);

    int ngroups = (rows + 15) >> 4;
    int gw = blockIdx.x * 4 + wid;
    int gstride = gridDim.x * 4;
    for (int g = gw; g < ngroups; g += gstride) {
        int rbase = g << 4;
        int rsub = lane >> 4;
#pragma unroll
        for (int j = 0; j < 8; j++) {
            int rloc = rsub + j * 2;
            int row = rbase + rloc; if (row >= rows) row = rows - 1;
            float4 v = *(const float4*)(xsrc + (size_t)row * 64 + cg * 4);
            __half* dstp = &sA[wid][rloc * LDA + cg * 4];
            *(__half2*)(dstp) = __floats2half2_rn(v.x, v.y);
            *(__half2*)(dstp + 2) = __floats2half2_rn(v.z, v.w);
        }
        __syncwarp();

        uint32_t afr[4][4];
#pragma unroll
        for (int kt = 0; kt < 4; kt++)
            ldsm_x4(afr[kt], aLdAddr + (uint32_t)(kt * 16 * 2));

        float c1[16][4];
#pragma unroll
        for (int nt = 0; nt < 16; nt++) {
            c1[nt][0] = 0.f; c1[nt][1] = 0.f; c1[nt][2] = 0.f; c1[nt][3] = 0.f;
#pragma unroll
            for (int kt = 0; kt < 4; kt++) {
                uint32_t b0, bq;
                uint32_t addr = b1U + (uint32_t)((((kt * 16) + bRow) * LDB1 + nt * 8) * 2);
                ldsm_x2t(b0, bq, addr);
                mma_16816(c1[nt], afr[kt], b0, bq);
            }
        }

        uint32_t a2[8][4];
#pragma unroll
        for (int nt = 0; nt < 16; nt++) {
            int n0 = nt * 8 + 2 * (lane & 3);
            float bx = sb1[n0], by = sb1[n0 + 1];
            __half2 lo = __floats2half2_rn(fmaxf(c1[nt][0] + bx, 0.f),
                                           fmaxf(c1[nt][1] + by, 0.f));
            __half2 hi = __floats2half2_rn(fmaxf(c1[nt][2] + bx, 0.f),
                                           fmaxf(c1[nt][3] + by, 0.f));
            int kt2 = nt >> 1, base = (nt & 1) * 2;
            a2[kt2][base]     = *reinterpret_cast<uint32_t*>(&lo);
            a2[kt2][base + 1] = *reinterpret_cast<uint32_t*>(&hi);
        }

        float c2[8][4];
#pragma unroll
        for (int nt = 0; nt < 8; nt++) {
            c2[nt][0] = 0.f; c2[nt][1] = 0.f; c2[nt][2] = 0.f; c2[nt][3] = 0.f;
#pragma unroll
            for (int kt = 0; kt < 8; kt++) {
                uint32_t b0, bq;
                uint32_t addr = b2U + (uint32_t)((((kt * 16) + bRow) * LDB2 + nt * 8) * 2);
                ldsm_x2t(b0, bq, addr);
                mma_16816(c2[nt], a2[kt], b0, bq);
            }
        }

        int r0 = rbase + (lane >> 2);
        int r1 = r0 + 8;
#pragma unroll
        for (int nt = 0; nt < 8; nt++) {
            int n = nt * 8 + 2 * (lane & 3);
            float bx = sb2[n], by = sb2[n + 1];
            if (r0 < rows) {
                float2 xv = *(const float2*)(xsrc + (size_t)r0 * 64 + n);
                *(float2*)(out + (size_t)r0 * 64 + n) =
                    make_float2(xv.x + bx + c2[nt][0], xv.y + by + c2[nt][1]);
            }
            if (r1 < rows) {
                float2 xv = *(const float2*)(xsrc + (size_t)r1 * 64 + n);
                *(float2*)(out + (size_t)r1 * 64 + n) =
                    make_float2(xv.x + bx + c2[nt][2], xv.y + by + c2[nt][3]);
            }
        }
        __syncwarp();
    }
}

// ---------------- host launcher -------------------------------------------------
extern "C" void kernel_launch(void* const* d_in, const int* in_sizes, int n_in,
                              void* d_out, int out_size) {
    int xAw, xAb, xBw, xBb, xCw, xCb, xDw, xDb, xEw, xEb;
    if (in_sizes[5] == 64) {  // dict order: Aw,Ab,Bw,Bb,Cw,Cb,Dw,Db,Ew,Eb
        xAw = 4; xAb = 5; xBw = 6; xBb = 7; xCw = 8; xCb = 9;
        xDw = 10; xDb = 11; xEw = 12; xEb = 13;
    } else {                  // signature order: Aw,Bw,Cw,Dw,Ew,Ab,Bb,Cb,Db,Eb
        xAw = 4; xBw = 5; xCw = 6; xDw = 7; xEw = 8;
        xAb = 9; xBb = 10; xCb = 11; xDb = 12; xEb = 13;
    }
    const float* h   = (const float*)d_in[0];
    const float* e   = (const float*)d_in[1];
    const int*   src = (const int*)d_in[2];
    const int*   dst = (const int*)d_in[3];
    const float* Aw = (const float*)d_in[xAw]; const float* Ab = (const float*)d_in[xAb];
    const float* Bw = (const float*)d_in[xBw]; const float* Bb = (const float*)d_in[xBb];
    const float* Cw = (const float*)d_in[xCw]; const float* Cb = (const float*)d_in[xCb];
    const float* Dw = (const float*)d_in[xDw]; const float* Db = (const float*)d_in[xDb];
    const float* Ew = (const float*)d_in[xEw]; const float* Eb = (const float*)d_in[xEb];
    const float* g1h = (const float*)d_in[14]; const float* g1e = (const float*)d_in[15];
    const float* g2h = (const float*)d_in[16]; const float* g2e = (const float*)d_in[17];
    const float* b1h = (const float*)d_in[18]; const float* b1e = (const float*)d_in[19];
    const float* b2h = (const float*)d_in[20]; const float* b2e = (const float*)d_in[21];
    const float* Wh1 = (const float*)d_in[22]; const float* bh1 = (const float*)d_in[23];
    const float* Wh2 = (const float*)d_in[24]; const float* bh2 = (const float*)d_in[25];
    const float* We1 = (const float*)d_in[26]; const float* be1 = (const float*)d_in[27];
    const float* We2 = (const float*)d_in[28]; const float* be2 = (const float*)d_in[29];
    float* out = (float*)d_out;

    int N = in_sizes[0] / 64;
    int E = in_sizes[2];

    cudaFuncSetAttribute(k_node_mma, cudaFuncAttributeMaxDynamicSharedMemorySize, 53248);

    k_zero<<<2048, 256>>>(N * 64);
    k_stats<<<512, 256>>>(h, N, 0);
    k_stats<<<2048, 256>>>(e, E, 1);
    k_finalize<<<1, 64>>>(0, g1h, b1h, 1.0f / (float)N);
    k_finalize<<<1, 64>>>(1, g1e, b1e, 1.0f / (float)E);
    k_fold5<<<5, 64>>>(Aw, Ab, Bw, Bb, Cw, Cb, Dw, Db, Ew, Eb);
    k_node_mma<<<391, 256, 52224>>>(h, N);
    k_edge_mma<<<1480, 256>>>(e, src, dst, E);
    k_h2<<<512, 256>>>(h, N);
    k_finalize<<<1, 64>>>(2, g2h, b2h, 1.0f / (float)N);
    k_finalize<<<1, 64>>>(3, g2e, b2e, 1.0f / (float)E);
    k_fold2<<<2, 128>>>(Wh1, bh1, We1, be1);
    k_ffn_mma<<<592, 128>>>(0, 5, Wh2, bh2, N, out);
    k_ffn_mma<<<592, 128>>>(1, 6, We2, be2, E, out + (size_t)N * 64);
}